// round 13
// baseline (speedup 1.0000x reference)
#include <cuda_runtime.h>
#include <cuda_fp16.h>
#include <cstdint>

// ---------------------------------------------------------------------------
// Problem constants
// ---------------------------------------------------------------------------
#define NN   8192
#define FIN  128
#define FHID 64
#define FOUT 2
#define KSPLIT1 4     // layer-1 aggregation split
#define INV255  (1.0f / 255.0f)

// ---------------------------------------------------------------------------
// Scratch (__device__ globals)
// ---------------------------------------------------------------------------
__device__ unsigned char g_adj8[(size_t)NN * NN];     // 64 MB u8 adjacency (x255)
__device__ float         g_d[NN];                      // d_inv_sqrt
__device__ __half        g_z1[NN * FHID];              // d ⊙ (x@W1)  [8192,64] fp16
__device__ float         g_z2f[NN * 2];                // d ⊙ (h@W2)  [8192,2] fp32
__device__ float         g_part1[KSPLIT1][NN][FHID];   // layer-1 split-K partials
__device__ int           g_cnt1[NN / 128];             // agg1 row-block arrival counters

// ---------------------------------------------------------------------------
// PTX helpers
// ---------------------------------------------------------------------------
__device__ __forceinline__ unsigned smem_u32(const void* p) {
    return (unsigned)__cvta_generic_to_shared(p);
}
__device__ __forceinline__ void cp16(void* dst, const void* src) {
    unsigned d = smem_u32(dst);
    asm volatile("cp.async.cg.shared.global [%0],[%1],16;\n" :: "r"(d), "l"(src));
}
__device__ __forceinline__ void cp_commit() {
    asm volatile("cp.async.commit_group;\n");
}
__device__ __forceinline__ void cp_wait_2() {
    asm volatile("cp.async.wait_group 2;\n");
}
__device__ __forceinline__ void ldmatrix_x4(uint32_t& a0, uint32_t& a1, uint32_t& a2, uint32_t& a3,
                                            unsigned addr) {
    asm volatile("ldmatrix.sync.aligned.m8n8.x4.shared.b16 {%0,%1,%2,%3},[%4];\n"
                 : "=r"(a0), "=r"(a1), "=r"(a2), "=r"(a3) : "r"(addr));
}
__device__ __forceinline__ void ldmatrix_x4_trans(uint32_t& a0, uint32_t& a1, uint32_t& a2, uint32_t& a3,
                                                  unsigned addr) {
    asm volatile("ldmatrix.sync.aligned.m8n8.x4.trans.shared.b16 {%0,%1,%2,%3},[%4];\n"
                 : "=r"(a0), "=r"(a1), "=r"(a2), "=r"(a3) : "r"(addr));
}
__device__ __forceinline__ void mma_f16(float c[4],
                                        uint32_t a0, uint32_t a1, uint32_t a2, uint32_t a3,
                                        uint32_t b0, uint32_t b1) {
    asm volatile("mma.sync.aligned.m16n8k16.row.col.f32.f16.f16.f32 "
                 "{%0,%1,%2,%3},{%4,%5,%6,%7},{%8,%9},{%0,%1,%2,%3};\n"
                 : "+f"(c[0]), "+f"(c[1]), "+f"(c[2]), "+f"(c[3])
                 : "r"(a0), "r"(a1), "r"(a2), "r"(a3), "r"(b0), "r"(b1));
}
// dequant one 8192-elem u8 stage into a [rows][72]-strided fp16 buffer, 256 thr
// fp16 bits (0x6400 | v) == 1024+v exactly; PRMT + add.f16x2(-1024) -> exact v.
__device__ __forceinline__ void dequant_stage(const unsigned char* A8s, __half* W,
                                              int warp, int lane) {
    const uint2* sflat = reinterpret_cast<const uint2*>(A8s);
    const uint32_t n1024x2 = 0xE400E400u;   // fp16x2 (-1024, -1024)
#pragma unroll
    for (int j = 0; j < 4; ++j) {
        int e0 = warp * 1024 + j * 256 + lane * 8;
        uint2 w = sflat[e0 >> 3];
        int r = e0 >> 6, col = e0 & 63;
        uint32_t o0 = __byte_perm(w.x, 0x64u, 0x4140);
        uint32_t o1 = __byte_perm(w.x, 0x64u, 0x4342);
        uint32_t o2 = __byte_perm(w.y, 0x64u, 0x4140);
        uint32_t o3 = __byte_perm(w.y, 0x64u, 0x4342);
        asm("add.f16x2 %0,%0,%1;" : "+r"(o0) : "r"(n1024x2));
        asm("add.f16x2 %0,%0,%1;" : "+r"(o1) : "r"(n1024x2));
        asm("add.f16x2 %0,%0,%1;" : "+r"(o2) : "r"(n1024x2));
        asm("add.f16x2 %0,%0,%1;" : "+r"(o3) : "r"(n1024x2));
        *reinterpret_cast<uint4*>(W + r * 72 + col) = make_uint4(o0, o1, o2, o3);
    }
}
__device__ __forceinline__ uint32_t quant4(float4 v) {
    return __float2uint_rn(v.x * 255.f)
         | (__float2uint_rn(v.y * 255.f) << 8)
         | (__float2uint_rn(v.z * 255.f) << 16)
         | (__float2uint_rn(v.w * 255.f) << 24);
}

// ---------------------------------------------------------------------------
// Kernel 1: row sums of adj (fp32) + quantize adj -> u8 (x255).
// One block per row (grid 8192); 64B per thread per iter (4 LDG.128 -> 1 STG.128).
// ---------------------------------------------------------------------------
__global__ __launch_bounds__(256) void k_rowsum_convert(const float* __restrict__ adj) {
    int row = blockIdx.x;
    const float4* src = reinterpret_cast<const float4*>(adj + (size_t)row * NN);
    uint4* dst = reinterpret_cast<uint4*>(g_adj8 + (size_t)row * NN);
    float s = 0.f;
#pragma unroll
    for (int it = 0; it < 2; ++it) {
        int base = it * 1024 + threadIdx.x * 4;   // float4 units
        float4 v0 = __ldcs(src + base);
        float4 v1 = __ldcs(src + base + 1);
        float4 v2 = __ldcs(src + base + 2);
        float4 v3 = __ldcs(src + base + 3);
        s += ((v0.x + v0.y) + (v0.z + v0.w)) + ((v1.x + v1.y) + (v1.z + v1.w))
           + ((v2.x + v2.y) + (v2.z + v2.w)) + ((v3.x + v3.y) + (v3.z + v3.w));
        uint4 o;
        o.x = quant4(v0); o.y = quant4(v1); o.z = quant4(v2); o.w = quant4(v3);
        dst[it * 256 + threadIdx.x] = o;
    }
    for (int o = 16; o; o >>= 1) s += __shfl_xor_sync(0xFFFFFFFFu, s, o);
    __shared__ float ws[8];
    if ((threadIdx.x & 31) == 0) ws[threadIdx.x >> 5] = s;
    __syncthreads();
    if (threadIdx.x == 0) {
        float t = 0.f;
#pragma unroll
        for (int w = 0; w < 8; ++w) t += ws[w];
        g_d[row] = rsqrtf(t + 1e-6f);
    }
}

// ---------------------------------------------------------------------------
// Kernel 2: z1 = fp16( d ⊙ (x @ W1) ).
// ---------------------------------------------------------------------------
__global__ __launch_bounds__(256) void k_xw1(const float* __restrict__ x,
                                             const float* __restrict__ W1) {
    __shared__ float W1s[FIN][FHID];
    __shared__ float xs[16][FIN];
    int tid = threadIdx.x;
    int r0 = blockIdx.x * 16;
    for (int i = tid; i < FIN * FHID; i += 256) W1s[i >> 6][i & 63] = W1[i];
    for (int i = tid; i < 16 * FIN; i += 256) xs[i >> 7][i & 127] = x[(size_t)r0 * FIN + i];
    __syncthreads();
    int f = tid & 63;
    int rb = tid >> 6;
    float acc[4] = {0.f, 0.f, 0.f, 0.f};
#pragma unroll
    for (int k = 0; k < FIN; ++k) {
        float w = W1s[k][f];
#pragma unroll
        for (int j = 0; j < 4; ++j) acc[j] += xs[rb + j * 4][k] * w;
    }
#pragma unroll
    for (int j = 0; j < 4; ++j) {
        int row = r0 + rb + j * 4;
        g_z1[row * FHID + f] = __float2half(g_d[row] * acc[j]);
    }
}

// ---------------------------------------------------------------------------
// Kernel 3: agg1 split-K + fused mid-epilogue (last CTA per row-block).
//   g_part1[ksl] = (1/255) * adj8[:, kslice] @ z1[kslice, :]
//   last CTA: h = relu(d*ΣU+b1); z2f = d ⊙ (h@W2)  (fp32)
// CTA tile 128x64, KT=64, pipelined cheap fp16 dequant (Wb ping-pong).
// ---------------------------------------------------------------------------
#define KT 64
#define ST 4
#define A1_STAGE (128 * 64)
#define WB_STRIDE (128 * 72)
#define B1_STRIDE (64 * 72)

__global__ __launch_bounds__(256) void k_agg1(const float* __restrict__ b1,
                                              const float* __restrict__ W2) {
    extern __shared__ __align__(16) unsigned char dyn[];
    unsigned char* A8 = dyn;                                             // [ST][A1_STAGE]
    __half* Wb = reinterpret_cast<__half*>(dyn + ST * A1_STAGE);         // [2][128][72]
    __half* Bb = Wb + 2 * WB_STRIDE;                                     // [ST][64][72]

    int tid = threadIdx.x;
    int warp = tid >> 5, lane = tid & 31;
    int wm = warp >> 1, wn = warp & 1;            // 4m x 2n warp grid
    int row0 = blockIdx.x * 128;
    int ksl = blockIdx.y;
    int kbase = ksl * (NN / KSPLIT1);             // 2048
    float acc[2][4][4] = {};
    const unsigned char* Ag = g_adj8 + (size_t)row0 * NN;

    auto load_tiles = [&](int s, int k0) {
        unsigned char* As = A8 + s * A1_STAGE;
        __half* Bs = Bb + s * B1_STRIDE;
#pragma unroll
        for (int i = 0; i < 2; ++i) {             // A: 128 rows x 64B
            int c = tid + i * 256;
            int r = c >> 2, col = (c & 3) * 16;
            cp16(As + r * 64 + col, Ag + (size_t)r * NN + k0 + col);
        }
#pragma unroll
        for (int i = 0; i < 2; ++i) {             // B: 64 rows x 128B
            int c = tid + i * 256;
            int r = c >> 3, col = (c & 7) * 8;
            cp16(Bs + r * 72 + col, g_z1 + (size_t)(k0 + r) * FHID + col);
        }
    };

#pragma unroll
    for (int s = 0; s < ST - 1; ++s) { load_tiles(s, kbase + s * KT); cp_commit(); }
    cp_wait_2();
    __syncthreads();
    dequant_stage(A8, Wb, warp, lane);            // stage 0 -> Wb[0]

    const int NIT = (NN / KSPLIT1) / KT;          // 32
    for (int it = 0; it < NIT; ++it) {
        if (it + 3 < NIT) load_tiles((it + 3) & (ST - 1), kbase + (it + 3) * KT);
        cp_commit();
        cp_wait_2();                              // stages <= it+1 arrived
        __syncthreads();                          // sync1

        if (it + 1 < NIT)                         // convert next stage (overlaps MMA issue)
            dequant_stage(A8 + ((it + 1) & (ST - 1)) * A1_STAGE,
                          Wb + ((it + 1) & 1) * WB_STRIDE, warp, lane);

        __half* As = Wb + (it & 1) * WB_STRIDE;
        __half* Bs = Bb + (it & (ST - 1)) * B1_STRIDE;
        int j = lane >> 3;                        // x4.trans lane group
#pragma unroll
        for (int ks = 0; ks < 4; ++ks) {
            uint32_t a[2][4], b[4][2];
#pragma unroll
            for (int mt = 0; mt < 2; ++mt) {
                unsigned ad = smem_u32(As + (wm * 32 + mt * 16 + (lane & 15)) * 72
                                          + ks * 16 + (lane >> 4) * 8);
                ldmatrix_x4(a[mt][0], a[mt][1], a[mt][2], a[mt][3], ad);
            }
#pragma unroll
            for (int nt2 = 0; nt2 < 2; ++nt2) {   // each x4.trans covers 2 nt tiles
                unsigned bd = smem_u32(Bs + (ks * 16 + (j & 1) * 8 + (lane & 7)) * 72
                                          + wn * 32 + nt2 * 16 + (j >> 1) * 8);
                ldmatrix_x4_trans(b[nt2 * 2][0], b[nt2 * 2][1],
                                  b[nt2 * 2 + 1][0], b[nt2 * 2 + 1][1], bd);
            }
#pragma unroll
            for (int mt = 0; mt < 2; ++mt)
#pragma unroll
                for (int nt = 0; nt < 4; ++nt)
                    mma_f16(acc[mt][nt], a[mt][0], a[mt][1], a[mt][2], a[mt][3],
                            b[nt][0], b[nt][1]);
        }
        __syncthreads();                          // sync2
    }

    // write fp32 partials (fold 1/255)
#pragma unroll
    for (int mt = 0; mt < 2; ++mt) {
#pragma unroll
        for (int nt = 0; nt < 4; ++nt) {
            int cbase = wn * 32 + nt * 8 + (lane & 3) * 2;
#pragma unroll
            for (int half = 0; half < 2; ++half) {
                int r = wm * 32 + mt * 16 + (lane >> 2) + half * 8;
                float2 v = make_float2(acc[mt][nt][half * 2 + 0] * INV255,
                                       acc[mt][nt][half * 2 + 1] * INV255);
                *reinterpret_cast<float2*>(&g_part1[ksl][row0 + r][cbase]) = v;
            }
        }
    }

    // last-CTA fused epilogue (z2f in fp32)
    __threadfence();
    __syncthreads();
    __shared__ int is_last;
    if (tid == 0) is_last = (atomicAdd(&g_cnt1[blockIdx.x], 1) == KSPLIT1 - 1);
    __syncthreads();
    if (!is_last) return;
    __threadfence();
    int seg = tid & 7;                            // 8 threads per row
#pragma unroll
    for (int rr = 0; rr < 4; ++rr) {
        int row = row0 + rr * 32 + (tid >> 3);
        float dd = g_d[row];
        float u[8] = {};
#pragma unroll
        for (int s = 0; s < KSPLIT1; ++s) {
            float4 a = *reinterpret_cast<const float4*>(&g_part1[s][row][seg * 8]);
            float4 b = *reinterpret_cast<const float4*>(&g_part1[s][row][seg * 8 + 4]);
            u[0] += a.x; u[1] += a.y; u[2] += a.z; u[3] += a.w;
            u[4] += b.x; u[5] += b.y; u[6] += b.z; u[7] += b.w;
        }
        float s0 = 0.f, s1 = 0.f;
#pragma unroll
        for (int jj = 0; jj < 8; ++jj) {
            int c = seg * 8 + jj;
            float h = fmaxf(dd * u[jj] + b1[c], 0.f);
            s0 += h * W2[c * 2 + 0];
            s1 += h * W2[c * 2 + 1];
        }
        for (int o = 4; o; o >>= 1) {
            s0 += __shfl_xor_sync(0xFFFFFFFFu, s0, o);
            s1 += __shfl_xor_sync(0xFFFFFFFFu, s1, o);
        }
        if (seg == 0)
            *reinterpret_cast<float2*>(&g_z2f[row * 2]) = make_float2(dd * s0, dd * s1);
    }
    if (tid == 0) g_cnt1[blockIdx.x] = 0;         // reset for next graph replay
}

// ---------------------------------------------------------------------------
// Kernel 4: agg2 direct fp32:  out = d ⊙ ((1/255)·adj8 @ z2f) + b2
// 256 threads, 8 warps x 4 rows = 32 rows/CTA -> grid 256, single wave.
// 4 rows/warp amortizes z2 LDS + dequant across more FFMA work.
// ---------------------------------------------------------------------------
__global__ __launch_bounds__(256) void k_agg2_fma(const float* __restrict__ b2,
                                                  float* __restrict__ out) {
    extern __shared__ __align__(16) unsigned char dyn[];
    float2* z2s = reinterpret_cast<float2*>(dyn);   // padded index k -> k + (k>>4)
    int tid = threadIdx.x, warp = tid >> 5, lane = tid & 31;

    // stage z2f (8192 float2) into padded smem
    {
        const uint4* src = reinterpret_cast<const uint4*>(g_z2f);
        for (int i = tid; i < NN / 2; i += 256) {
            uint4 v = src[i];
            int k = i * 2;
            int kp = k + (k >> 4);
            *reinterpret_cast<uint2*>(&z2s[kp])     = make_uint2(v.x, v.y);
            *reinterpret_cast<uint2*>(&z2s[kp + 1]) = make_uint2(v.z, v.w);
        }
    }
    __syncthreads();

    int row0 = blockIdx.x * 32 + warp * 4;
    const unsigned char* Ar = g_adj8 + (size_t)row0 * NN;
    float acc[4][2] = {};

#pragma unroll 2
    for (int t = 0; t < 16; ++t) {
        uint4 aw[4];
#pragma unroll
        for (int q = 0; q < 4; ++q)
            aw[q] = *reinterpret_cast<const uint4*>(Ar + (size_t)q * NN + t * 512 + lane * 16);
        int kbase = t * 512 + lane * 16;
        int kp = kbase + (kbase >> 4);
#pragma unroll
        for (int e = 0; e < 16; ++e) {
            float2 z = z2s[kp + e];
            const int wi = e >> 2, bi = e & 3;
#pragma unroll
            for (int q = 0; q < 4; ++q) {
                uint32_t wv = (wi == 0) ? aw[q].x : (wi == 1) ? aw[q].y
                            : (wi == 2) ? aw[q].z : aw[q].w;
                float f = __uint_as_float(__byte_perm(wv, 0x4B000000u, 0x7540u | bi))
                          - 8388608.f;
                acc[q][0] = fmaf(f, z.x, acc[q][0]);
                acc[q][1] = fmaf(f, z.y, acc[q][1]);
            }
        }
    }

    // warp reduce (each lane holds a disjoint K-subset partial)
#pragma unroll
    for (int q = 0; q < 4; ++q)
#pragma unroll
        for (int c = 0; c < 2; ++c)
            for (int o = 16; o; o >>= 1)
                acc[q][c] += __shfl_xor_sync(0xFFFFFFFFu, acc[q][c], o);

    if (lane == 0) {
        float bb0 = b2[0], bb1 = b2[1];
#pragma unroll
        for (int q = 0; q < 4; ++q) {
            int r = row0 + q;
            float dd = g_d[r] * INV255;
            *reinterpret_cast<float2*>(&out[r * 2]) =
                make_float2(dd * acc[q][0] + bb0, dd * acc[q][1] + bb1);
        }
    }
}

// ---------------------------------------------------------------------------
// Launch
// ---------------------------------------------------------------------------
extern "C" void kernel_launch(void* const* d_in, const int* in_sizes, int n_in,
                              void* d_out, int out_size) {
    const float *x = nullptr, *adj = nullptr, *W1 = nullptr, *b1 = nullptr,
                *W2 = nullptr, *b2 = nullptr;
    for (int i = 0; i < n_in; ++i) {
        switch (in_sizes[i]) {
            case NN * FIN:    x   = (const float*)d_in[i]; break;
            case 67108864:    adj = (const float*)d_in[i]; break;
            case FIN * FHID:  W1  = (const float*)d_in[i]; break;
            case FHID:        b1  = (const float*)d_in[i]; break;
            case FHID * FOUT: W2  = (const float*)d_in[i]; break;
            case FOUT:        b2  = (const float*)d_in[i]; break;
            default: break;
        }
    }
    float* out = (float*)d_out;

    const int smem1 = ST * A1_STAGE + 2 * WB_STRIDE * 2 + ST * B1_STRIDE * 2;  // 106496
    const int smem2 = (NN + NN / 16) * 8;                                       // 69632
    cudaFuncSetAttribute(k_agg1, cudaFuncAttributeMaxDynamicSharedMemorySize, smem1);
    cudaFuncSetAttribute(k_agg2_fma, cudaFuncAttributeMaxDynamicSharedMemorySize, smem2);

    k_rowsum_convert<<<NN, 256>>>(adj);
    k_xw1<<<NN / 16, 256>>>(x, W1);
    k_agg1<<<dim3(NN / 128, KSPLIT1), 256, smem1>>>(b1, W2);
    k_agg2_fma<<<NN / 32, 256, smem2>>>(b2, out);
}

// round 14
// speedup vs baseline: 1.0204x; 1.0204x over previous
#include <cuda_runtime.h>
#include <cuda_fp16.h>
#include <cstdint>

// ---------------------------------------------------------------------------
// Problem constants
// ---------------------------------------------------------------------------
#define NN   8192
#define FIN  128
#define FHID 64
#define FOUT 2
#define KSPLIT1 4     // layer-1 aggregation split
#define INV255  (1.0f / 255.0f)

// ---------------------------------------------------------------------------
// Scratch (__device__ globals)
// ---------------------------------------------------------------------------
__device__ unsigned char g_adj8[(size_t)NN * NN];     // 64 MB u8 adjacency (x255)
__device__ float         g_d[NN];                      // d_inv_sqrt
__device__ __half        g_z1[NN * FHID];              // d ⊙ (x@W1)  [8192,64] fp16
__device__ float         g_z2f[NN * 2];                // d ⊙ (h@W2)  [8192,2] fp32
__device__ float         g_part1[KSPLIT1][NN][FHID];   // layer-1 split-K partials
__device__ int           g_cnt1[NN / 128];             // agg1 row-block arrival counters

// ---------------------------------------------------------------------------
// PTX helpers
// ---------------------------------------------------------------------------
__device__ __forceinline__ unsigned smem_u32(const void* p) {
    return (unsigned)__cvta_generic_to_shared(p);
}
__device__ __forceinline__ void cp16(void* dst, const void* src) {
    unsigned d = smem_u32(dst);
    asm volatile("cp.async.cg.shared.global [%0],[%1],16;\n" :: "r"(d), "l"(src));
}
__device__ __forceinline__ void cp_commit() {
    asm volatile("cp.async.commit_group;\n");
}
__device__ __forceinline__ void cp_wait_2() {
    asm volatile("cp.async.wait_group 2;\n");
}
__device__ __forceinline__ void ldmatrix_x4(uint32_t& a0, uint32_t& a1, uint32_t& a2, uint32_t& a3,
                                            unsigned addr) {
    asm volatile("ldmatrix.sync.aligned.m8n8.x4.shared.b16 {%0,%1,%2,%3},[%4];\n"
                 : "=r"(a0), "=r"(a1), "=r"(a2), "=r"(a3) : "r"(addr));
}
__device__ __forceinline__ void ldmatrix_x4_trans(uint32_t& a0, uint32_t& a1, uint32_t& a2, uint32_t& a3,
                                                  unsigned addr) {
    asm volatile("ldmatrix.sync.aligned.m8n8.x4.trans.shared.b16 {%0,%1,%2,%3},[%4];\n"
                 : "=r"(a0), "=r"(a1), "=r"(a2), "=r"(a3) : "r"(addr));
}
__device__ __forceinline__ void mma_f16(float c[4],
                                        uint32_t a0, uint32_t a1, uint32_t a2, uint32_t a3,
                                        uint32_t b0, uint32_t b1) {
    asm volatile("mma.sync.aligned.m16n8k16.row.col.f32.f16.f16.f32 "
                 "{%0,%1,%2,%3},{%4,%5,%6,%7},{%8,%9},{%0,%1,%2,%3};\n"
                 : "+f"(c[0]), "+f"(c[1]), "+f"(c[2]), "+f"(c[3])
                 : "r"(a0), "r"(a1), "r"(a2), "r"(a3), "r"(b0), "r"(b1));
}
// dequant one 8192-elem u8 stage into a [rows][72]-strided fp16 buffer, 256 thr
// fp16 bits (0x6400 | v) == 1024+v exactly; PRMT + add.f16x2(-1024) -> exact v.
__device__ __forceinline__ void dequant_stage(const unsigned char* A8s, __half* W,
                                              int warp, int lane) {
    const uint2* sflat = reinterpret_cast<const uint2*>(A8s);
    const uint32_t n1024x2 = 0xE400E400u;   // fp16x2 (-1024, -1024)
#pragma unroll
    for (int j = 0; j < 4; ++j) {
        int e0 = warp * 1024 + j * 256 + lane * 8;
        uint2 w = sflat[e0 >> 3];
        int r = e0 >> 6, col = e0 & 63;
        uint32_t o0 = __byte_perm(w.x, 0x64u, 0x4140);
        uint32_t o1 = __byte_perm(w.x, 0x64u, 0x4342);
        uint32_t o2 = __byte_perm(w.y, 0x64u, 0x4140);
        uint32_t o3 = __byte_perm(w.y, 0x64u, 0x4342);
        asm("add.f16x2 %0,%0,%1;" : "+r"(o0) : "r"(n1024x2));
        asm("add.f16x2 %0,%0,%1;" : "+r"(o1) : "r"(n1024x2));
        asm("add.f16x2 %0,%0,%1;" : "+r"(o2) : "r"(n1024x2));
        asm("add.f16x2 %0,%0,%1;" : "+r"(o3) : "r"(n1024x2));
        *reinterpret_cast<uint4*>(W + r * 72 + col) = make_uint4(o0, o1, o2, o3);
    }
}
__device__ __forceinline__ uint32_t quant4(float4 v) {
    return __float2uint_rn(v.x * 255.f)
         | (__float2uint_rn(v.y * 255.f) << 8)
         | (__float2uint_rn(v.z * 255.f) << 16)
         | (__float2uint_rn(v.w * 255.f) << 24);
}

// ---------------------------------------------------------------------------
// Kernel 1: row sums of adj (fp32) + quantize adj -> u8 (x255).
// One block per row (grid 8192); 64B per thread per iter (4 LDG.128 -> 1 STG.128).
// ---------------------------------------------------------------------------
__global__ __launch_bounds__(256) void k_rowsum_convert(const float* __restrict__ adj) {
    int row = blockIdx.x;
    const float4* src = reinterpret_cast<const float4*>(adj + (size_t)row * NN);
    uint4* dst = reinterpret_cast<uint4*>(g_adj8 + (size_t)row * NN);
    float s = 0.f;
#pragma unroll
    for (int it = 0; it < 2; ++it) {
        int base = it * 1024 + threadIdx.x * 4;   // float4 units
        float4 v0 = __ldcs(src + base);
        float4 v1 = __ldcs(src + base + 1);
        float4 v2 = __ldcs(src + base + 2);
        float4 v3 = __ldcs(src + base + 3);
        s += ((v0.x + v0.y) + (v0.z + v0.w)) + ((v1.x + v1.y) + (v1.z + v1.w))
           + ((v2.x + v2.y) + (v2.z + v2.w)) + ((v3.x + v3.y) + (v3.z + v3.w));
        uint4 o;
        o.x = quant4(v0); o.y = quant4(v1); o.z = quant4(v2); o.w = quant4(v3);
        dst[it * 256 + threadIdx.x] = o;
    }
    for (int o = 16; o; o >>= 1) s += __shfl_xor_sync(0xFFFFFFFFu, s, o);
    __shared__ float ws[8];
    if ((threadIdx.x & 31) == 0) ws[threadIdx.x >> 5] = s;
    __syncthreads();
    if (threadIdx.x == 0) {
        float t = 0.f;
#pragma unroll
        for (int w = 0; w < 8; ++w) t += ws[w];
        g_d[row] = rsqrtf(t + 1e-6f);
    }
}

// ---------------------------------------------------------------------------
// Kernel 2: z1 = fp16( d ⊙ (x @ W1) ).
// ---------------------------------------------------------------------------
__global__ __launch_bounds__(256) void k_xw1(const float* __restrict__ x,
                                             const float* __restrict__ W1) {
    __shared__ float W1s[FIN][FHID];
    __shared__ float xs[16][FIN];
    int tid = threadIdx.x;
    int r0 = blockIdx.x * 16;
    for (int i = tid; i < FIN * FHID; i += 256) W1s[i >> 6][i & 63] = W1[i];
    for (int i = tid; i < 16 * FIN; i += 256) xs[i >> 7][i & 127] = x[(size_t)r0 * FIN + i];
    __syncthreads();
    int f = tid & 63;
    int rb = tid >> 6;
    float acc[4] = {0.f, 0.f, 0.f, 0.f};
#pragma unroll
    for (int k = 0; k < FIN; ++k) {
        float w = W1s[k][f];
#pragma unroll
        for (int j = 0; j < 4; ++j) acc[j] += xs[rb + j * 4][k] * w;
    }
#pragma unroll
    for (int j = 0; j < 4; ++j) {
        int row = r0 + rb + j * 4;
        g_z1[row * FHID + f] = __float2half(g_d[row] * acc[j]);
    }
}

// ---------------------------------------------------------------------------
// Kernel 3: agg1 split-K + fused mid-epilogue (last CTA per row-block).
//   g_part1[ksl] = (1/255) * adj8[:, kslice] @ z1[kslice, :]
//   last CTA: h = relu(d*ΣU+b1); z2f = d ⊙ (h@W2)  (fp32)
// CTA tile 128x64, KT=64, pipelined cheap fp16 dequant (Wb ping-pong).
// ---------------------------------------------------------------------------
#define KT 64
#define ST 4
#define A1_STAGE (128 * 64)
#define WB_STRIDE (128 * 72)
#define B1_STRIDE (64 * 72)

__global__ __launch_bounds__(256) void k_agg1(const float* __restrict__ b1,
                                              const float* __restrict__ W2) {
    extern __shared__ __align__(16) unsigned char dyn[];
    unsigned char* A8 = dyn;                                             // [ST][A1_STAGE]
    __half* Wb = reinterpret_cast<__half*>(dyn + ST * A1_STAGE);         // [2][128][72]
    __half* Bb = Wb + 2 * WB_STRIDE;                                     // [ST][64][72]

    int tid = threadIdx.x;
    int warp = tid >> 5, lane = tid & 31;
    int wm = warp >> 1, wn = warp & 1;            // 4m x 2n warp grid
    int row0 = blockIdx.x * 128;
    int ksl = blockIdx.y;
    int kbase = ksl * (NN / KSPLIT1);             // 2048
    float acc[2][4][4] = {};
    const unsigned char* Ag = g_adj8 + (size_t)row0 * NN;

    auto load_tiles = [&](int s, int k0) {
        unsigned char* As = A8 + s * A1_STAGE;
        __half* Bs = Bb + s * B1_STRIDE;
#pragma unroll
        for (int i = 0; i < 2; ++i) {             // A: 128 rows x 64B
            int c = tid + i * 256;
            int r = c >> 2, col = (c & 3) * 16;
            cp16(As + r * 64 + col, Ag + (size_t)r * NN + k0 + col);
        }
#pragma unroll
        for (int i = 0; i < 2; ++i) {             // B: 64 rows x 128B
            int c = tid + i * 256;
            int r = c >> 3, col = (c & 7) * 8;
            cp16(Bs + r * 72 + col, g_z1 + (size_t)(k0 + r) * FHID + col);
        }
    };

#pragma unroll
    for (int s = 0; s < ST - 1; ++s) { load_tiles(s, kbase + s * KT); cp_commit(); }
    cp_wait_2();
    __syncthreads();
    dequant_stage(A8, Wb, warp, lane);            // stage 0 -> Wb[0]

    const int NIT = (NN / KSPLIT1) / KT;          // 32
    for (int it = 0; it < NIT; ++it) {
        if (it + 3 < NIT) load_tiles((it + 3) & (ST - 1), kbase + (it + 3) * KT);
        cp_commit();
        cp_wait_2();                              // stages <= it+1 arrived
        __syncthreads();                          // sync1

        if (it + 1 < NIT)                         // convert next stage (overlaps MMA issue)
            dequant_stage(A8 + ((it + 1) & (ST - 1)) * A1_STAGE,
                          Wb + ((it + 1) & 1) * WB_STRIDE, warp, lane);

        __half* As = Wb + (it & 1) * WB_STRIDE;
        __half* Bs = Bb + (it & (ST - 1)) * B1_STRIDE;
        int j = lane >> 3;                        // x4.trans lane group
#pragma unroll
        for (int ks = 0; ks < 4; ++ks) {
            uint32_t a[2][4], b[4][2];
#pragma unroll
            for (int mt = 0; mt < 2; ++mt) {
                unsigned ad = smem_u32(As + (wm * 32 + mt * 16 + (lane & 15)) * 72
                                          + ks * 16 + (lane >> 4) * 8);
                ldmatrix_x4(a[mt][0], a[mt][1], a[mt][2], a[mt][3], ad);
            }
#pragma unroll
            for (int nt2 = 0; nt2 < 2; ++nt2) {   // each x4.trans covers 2 nt tiles
                unsigned bd = smem_u32(Bs + (ks * 16 + (j & 1) * 8 + (lane & 7)) * 72
                                          + wn * 32 + nt2 * 16 + (j >> 1) * 8);
                ldmatrix_x4_trans(b[nt2 * 2][0], b[nt2 * 2][1],
                                  b[nt2 * 2 + 1][0], b[nt2 * 2 + 1][1], bd);
            }
#pragma unroll
            for (int mt = 0; mt < 2; ++mt)
#pragma unroll
                for (int nt = 0; nt < 4; ++nt)
                    mma_f16(acc[mt][nt], a[mt][0], a[mt][1], a[mt][2], a[mt][3],
                            b[nt][0], b[nt][1]);
        }
        __syncthreads();                          // sync2
    }

    // write fp32 partials (fold 1/255)
#pragma unroll
    for (int mt = 0; mt < 2; ++mt) {
#pragma unroll
        for (int nt = 0; nt < 4; ++nt) {
            int cbase = wn * 32 + nt * 8 + (lane & 3) * 2;
#pragma unroll
            for (int half = 0; half < 2; ++half) {
                int r = wm * 32 + mt * 16 + (lane >> 2) + half * 8;
                float2 v = make_float2(acc[mt][nt][half * 2 + 0] * INV255,
                                       acc[mt][nt][half * 2 + 1] * INV255);
                *reinterpret_cast<float2*>(&g_part1[ksl][row0 + r][cbase]) = v;
            }
        }
    }

    // last-CTA fused epilogue (z2f in fp32)
    __threadfence();
    __syncthreads();
    __shared__ int is_last;
    if (tid == 0) is_last = (atomicAdd(&g_cnt1[blockIdx.x], 1) == KSPLIT1 - 1);
    __syncthreads();
    if (!is_last) return;
    __threadfence();
    int seg = tid & 7;                            // 8 threads per row
#pragma unroll
    for (int rr = 0; rr < 4; ++rr) {
        int row = row0 + rr * 32 + (tid >> 3);
        float dd = g_d[row];
        float u[8] = {};
#pragma unroll
        for (int s = 0; s < KSPLIT1; ++s) {
            float4 a = *reinterpret_cast<const float4*>(&g_part1[s][row][seg * 8]);
            float4 b = *reinterpret_cast<const float4*>(&g_part1[s][row][seg * 8 + 4]);
            u[0] += a.x; u[1] += a.y; u[2] += a.z; u[3] += a.w;
            u[4] += b.x; u[5] += b.y; u[6] += b.z; u[7] += b.w;
        }
        float s0 = 0.f, s1 = 0.f;
#pragma unroll
        for (int jj = 0; jj < 8; ++jj) {
            int c = seg * 8 + jj;
            float h = fmaxf(dd * u[jj] + b1[c], 0.f);
            s0 += h * W2[c * 2 + 0];
            s1 += h * W2[c * 2 + 1];
        }
        for (int o = 4; o; o >>= 1) {
            s0 += __shfl_xor_sync(0xFFFFFFFFu, s0, o);
            s1 += __shfl_xor_sync(0xFFFFFFFFu, s1, o);
        }
        if (seg == 0)
            *reinterpret_cast<float2*>(&g_z2f[row * 2]) = make_float2(dd * s0, dd * s1);
    }
    if (tid == 0) g_cnt1[blockIdx.x] = 0;         // reset for next graph replay
}

// ---------------------------------------------------------------------------
// Kernel 4: agg2 direct fp32:  out = d ⊙ ((1/255)·adj8 @ z2f) + b2
// 512 threads, 32 rows/CTA (16 warps x 2 rows) -> grid 256, single wave.
// t-loop unrolled x2 for LDG MLP.
// ---------------------------------------------------------------------------
__global__ __launch_bounds__(512) void k_agg2_fma(const float* __restrict__ b2,
                                                  float* __restrict__ out) {
    extern __shared__ __align__(16) unsigned char dyn[];
    float2* z2s = reinterpret_cast<float2*>(dyn);   // padded index k -> k + (k>>4)
    int tid = threadIdx.x, warp = tid >> 5, lane = tid & 31;

    // stage z2f (8192 float2) into padded smem
    {
        const uint4* src = reinterpret_cast<const uint4*>(g_z2f);
        for (int i = tid; i < NN / 2; i += 512) {
            uint4 v = src[i];
            int k = i * 2;
            int kp = k + (k >> 4);
            *reinterpret_cast<uint2*>(&z2s[kp])     = make_uint2(v.x, v.y);
            *reinterpret_cast<uint2*>(&z2s[kp + 1]) = make_uint2(v.z, v.w);
        }
    }
    __syncthreads();

    int row0 = blockIdx.x * 32 + warp * 2;
    const unsigned char* Ar = g_adj8 + (size_t)row0 * NN;
    float acc[2][2] = {};

#pragma unroll 2
    for (int t = 0; t < 16; ++t) {
        uint4 aw[2];
#pragma unroll
        for (int q = 0; q < 2; ++q)
            aw[q] = *reinterpret_cast<const uint4*>(Ar + (size_t)q * NN + t * 512 + lane * 16);
        int kbase = t * 512 + lane * 16;
        int kp = kbase + (kbase >> 4);
#pragma unroll
        for (int e = 0; e < 16; ++e) {
            float2 z = z2s[kp + e];
            const int wi = e >> 2, bi = e & 3;
#pragma unroll
            for (int q = 0; q < 2; ++q) {
                uint32_t wv = (wi == 0) ? aw[q].x : (wi == 1) ? aw[q].y
                            : (wi == 2) ? aw[q].z : aw[q].w;
                float f = __uint_as_float(__byte_perm(wv, 0x4B000000u, 0x7540u | bi))
                          - 8388608.f;
                acc[q][0] = fmaf(f, z.x, acc[q][0]);
                acc[q][1] = fmaf(f, z.y, acc[q][1]);
            }
        }
    }

    // warp reduce (each lane holds a disjoint K-subset partial)
#pragma unroll
    for (int q = 0; q < 2; ++q)
#pragma unroll
        for (int c = 0; c < 2; ++c)
            for (int o = 16; o; o >>= 1)
                acc[q][c] += __shfl_xor_sync(0xFFFFFFFFu, acc[q][c], o);

    if (lane == 0) {
        float bb0 = b2[0], bb1 = b2[1];
#pragma unroll
        for (int q = 0; q < 2; ++q) {
            int r = row0 + q;
            float dd = g_d[r] * INV255;
            *reinterpret_cast<float2*>(&out[r * 2]) =
                make_float2(dd * acc[q][0] + bb0, dd * acc[q][1] + bb1);
        }
    }
}

// ---------------------------------------------------------------------------
// Launch
// ---------------------------------------------------------------------------
extern "C" void kernel_launch(void* const* d_in, const int* in_sizes, int n_in,
                              void* d_out, int out_size) {
    const float *x = nullptr, *adj = nullptr, *W1 = nullptr, *b1 = nullptr,
                *W2 = nullptr, *b2 = nullptr;
    for (int i = 0; i < n_in; ++i) {
        switch (in_sizes[i]) {
            case NN * FIN:    x   = (const float*)d_in[i]; break;
            case 67108864:    adj = (const float*)d_in[i]; break;
            case FIN * FHID:  W1  = (const float*)d_in[i]; break;
            case FHID:        b1  = (const float*)d_in[i]; break;
            case FHID * FOUT: W2  = (const float*)d_in[i]; break;
            case FOUT:        b2  = (const float*)d_in[i]; break;
            default: break;
        }
    }
    float* out = (float*)d_out;

    const int smem1 = ST * A1_STAGE + 2 * WB_STRIDE * 2 + ST * B1_STRIDE * 2;  // 106496
    const int smem2 = (NN + NN / 16) * 8;                                       // 69632
    cudaFuncSetAttribute(k_agg1, cudaFuncAttributeMaxDynamicSharedMemorySize, smem1);
    cudaFuncSetAttribute(k_agg2_fma, cudaFuncAttributeMaxDynamicSharedMemorySize, smem2);

    k_rowsum_convert<<<NN, 256>>>(adj);
    k_xw1<<<NN / 16, 256>>>(x, W1);
    k_agg1<<<dim3(NN / 128, KSPLIT1), 256, smem1>>>(b1, W2);
    k_agg2_fma<<<NN / 32, 512, smem2>>>(b2, out);
}

// round 15
// speedup vs baseline: 1.0497x; 1.0287x over previous
#include <cuda_runtime.h>
#include <cuda_fp16.h>
#include <cstdint>

// ---------------------------------------------------------------------------
// Problem constants
// ---------------------------------------------------------------------------
#define NN   8192
#define FIN  128
#define FHID 64
#define FOUT 2
#define KSPLIT1 4     // layer-1 aggregation split
#define INV255  (1.0f / 255.0f)

// ---------------------------------------------------------------------------
// Scratch (__device__ globals)
// ---------------------------------------------------------------------------
__device__ unsigned char g_adj8[(size_t)NN * NN];     // 64 MB u8 adjacency (x255)
__device__ float         g_d[NN];                      // d_inv_sqrt
__device__ __half        g_z1[NN * FHID];              // d ⊙ (x@W1)  [8192,64] fp16
__device__ float         g_z2f[NN * 2];                // d ⊙ (h@W2)  [8192,2] fp32
__device__ float         g_part1[KSPLIT1][NN][FHID];   // layer-1 split-K partials
__device__ int           g_cnt1[NN / 128];             // agg1 row-block arrival counters

// ---------------------------------------------------------------------------
// PTX helpers
// ---------------------------------------------------------------------------
__device__ __forceinline__ unsigned smem_u32(const void* p) {
    return (unsigned)__cvta_generic_to_shared(p);
}
__device__ __forceinline__ void cp16(void* dst, const void* src) {
    unsigned d = smem_u32(dst);
    asm volatile("cp.async.cg.shared.global [%0],[%1],16;\n" :: "r"(d), "l"(src));
}
__device__ __forceinline__ void cp_commit() {
    asm volatile("cp.async.commit_group;\n");
}
__device__ __forceinline__ void cp_wait_2() {
    asm volatile("cp.async.wait_group 2;\n");
}
__device__ __forceinline__ void ldmatrix_x4(uint32_t& a0, uint32_t& a1, uint32_t& a2, uint32_t& a3,
                                            unsigned addr) {
    asm volatile("ldmatrix.sync.aligned.m8n8.x4.shared.b16 {%0,%1,%2,%3},[%4];\n"
                 : "=r"(a0), "=r"(a1), "=r"(a2), "=r"(a3) : "r"(addr));
}
__device__ __forceinline__ void ldmatrix_x4_trans(uint32_t& a0, uint32_t& a1, uint32_t& a2, uint32_t& a3,
                                                  unsigned addr) {
    asm volatile("ldmatrix.sync.aligned.m8n8.x4.trans.shared.b16 {%0,%1,%2,%3},[%4];\n"
                 : "=r"(a0), "=r"(a1), "=r"(a2), "=r"(a3) : "r"(addr));
}
__device__ __forceinline__ void mma_f16(float c[4],
                                        uint32_t a0, uint32_t a1, uint32_t a2, uint32_t a3,
                                        uint32_t b0, uint32_t b1) {
    asm volatile("mma.sync.aligned.m16n8k16.row.col.f32.f16.f16.f32 "
                 "{%0,%1,%2,%3},{%4,%5,%6,%7},{%8,%9},{%0,%1,%2,%3};\n"
                 : "+f"(c[0]), "+f"(c[1]), "+f"(c[2]), "+f"(c[3])
                 : "r"(a0), "r"(a1), "r"(a2), "r"(a3), "r"(b0), "r"(b1));
}
// dequant one 8192-elem u8 stage into a [rows][72]-strided fp16 buffer, 256 thr
// fp16 bits (0x6400 | v) == 1024+v exactly; PRMT + add.f16x2(-1024) -> exact v.
__device__ __forceinline__ void dequant_stage(const unsigned char* A8s, __half* W,
                                              int warp, int lane) {
    const uint2* sflat = reinterpret_cast<const uint2*>(A8s);
    const uint32_t n1024x2 = 0xE400E400u;   // fp16x2 (-1024, -1024)
#pragma unroll
    for (int j = 0; j < 4; ++j) {
        int e0 = warp * 1024 + j * 256 + lane * 8;
        uint2 w = sflat[e0 >> 3];
        int r = e0 >> 6, col = e0 & 63;
        uint32_t o0 = __byte_perm(w.x, 0x64u, 0x4140);
        uint32_t o1 = __byte_perm(w.x, 0x64u, 0x4342);
        uint32_t o2 = __byte_perm(w.y, 0x64u, 0x4140);
        uint32_t o3 = __byte_perm(w.y, 0x64u, 0x4342);
        asm("add.f16x2 %0,%0,%1;" : "+r"(o0) : "r"(n1024x2));
        asm("add.f16x2 %0,%0,%1;" : "+r"(o1) : "r"(n1024x2));
        asm("add.f16x2 %0,%0,%1;" : "+r"(o2) : "r"(n1024x2));
        asm("add.f16x2 %0,%0,%1;" : "+r"(o3) : "r"(n1024x2));
        *reinterpret_cast<uint4*>(W + r * 72 + col) = make_uint4(o0, o1, o2, o3);
    }
}
__device__ __forceinline__ uint32_t quant4(float4 v) {
    return __float2uint_rn(v.x * 255.f)
         | (__float2uint_rn(v.y * 255.f) << 8)
         | (__float2uint_rn(v.z * 255.f) << 16)
         | (__float2uint_rn(v.w * 255.f) << 24);
}

// ---------------------------------------------------------------------------
// Kernel 1: row sums of adj (fp32) + quantize adj -> u8 (x255).
// One block per row (grid 8192), 512 threads, exactly one 64B chunk per thread.
// ---------------------------------------------------------------------------
__global__ __launch_bounds__(512) void k_rowsum_convert(const float* __restrict__ adj) {
    int row = blockIdx.x;
    const float4* src = reinterpret_cast<const float4*>(adj + (size_t)row * NN);
    uint4* dst = reinterpret_cast<uint4*>(g_adj8 + (size_t)row * NN);
    int base = threadIdx.x * 4;                  // float4 units
    float4 v0 = __ldcs(src + base);
    float4 v1 = __ldcs(src + base + 1);
    float4 v2 = __ldcs(src + base + 2);
    float4 v3 = __ldcs(src + base + 3);
    float s = ((v0.x + v0.y) + (v0.z + v0.w)) + ((v1.x + v1.y) + (v1.z + v1.w))
            + ((v2.x + v2.y) + (v2.z + v2.w)) + ((v3.x + v3.y) + (v3.z + v3.w));
    uint4 o;
    o.x = quant4(v0); o.y = quant4(v1); o.z = quant4(v2); o.w = quant4(v3);
    dst[threadIdx.x] = o;

    for (int off = 16; off; off >>= 1) s += __shfl_xor_sync(0xFFFFFFFFu, s, off);
    __shared__ float ws[16];
    if ((threadIdx.x & 31) == 0) ws[threadIdx.x >> 5] = s;
    __syncthreads();
    if (threadIdx.x == 0) {
        float t = 0.f;
#pragma unroll
        for (int w = 0; w < 16; ++w) t += ws[w];
        g_d[row] = rsqrtf(t + 1e-6f);
    }
}

// ---------------------------------------------------------------------------
// Kernel 2: z1 = fp16( d ⊙ (x @ W1) ).
// ---------------------------------------------------------------------------
__global__ __launch_bounds__(256) void k_xw1(const float* __restrict__ x,
                                             const float* __restrict__ W1) {
    __shared__ float W1s[FIN][FHID];
    __shared__ float xs[16][FIN];
    int tid = threadIdx.x;
    int r0 = blockIdx.x * 16;
    for (int i = tid; i < FIN * FHID; i += 256) W1s[i >> 6][i & 63] = W1[i];
    for (int i = tid; i < 16 * FIN; i += 256) xs[i >> 7][i & 127] = x[(size_t)r0 * FIN + i];
    __syncthreads();
    int f = tid & 63;
    int rb = tid >> 6;
    float acc[4] = {0.f, 0.f, 0.f, 0.f};
#pragma unroll
    for (int k = 0; k < FIN; ++k) {
        float w = W1s[k][f];
#pragma unroll
        for (int j = 0; j < 4; ++j) acc[j] += xs[rb + j * 4][k] * w;
    }
#pragma unroll
    for (int j = 0; j < 4; ++j) {
        int row = r0 + rb + j * 4;
        g_z1[row * FHID + f] = __float2half(g_d[row] * acc[j]);
    }
}

// ---------------------------------------------------------------------------
// Kernel 3: agg1 split-K + fused mid-epilogue (last CTA per row-block).
//   g_part1[ksl] = (1/255) * adj8[:, kslice] @ z1[kslice, :]
//   last CTA: h = relu(d*ΣU+b1); z2f = d ⊙ (h@W2)  (fp32)
// CTA tile 128x64, KT=64, pipelined cheap fp16 dequant (Wb ping-pong).
// ---------------------------------------------------------------------------
#define KT 64
#define ST 4
#define A1_STAGE (128 * 64)
#define WB_STRIDE (128 * 72)
#define B1_STRIDE (64 * 72)

__global__ __launch_bounds__(256) void k_agg1(const float* __restrict__ b1,
                                              const float* __restrict__ W2) {
    extern __shared__ __align__(16) unsigned char dyn[];
    unsigned char* A8 = dyn;                                             // [ST][A1_STAGE]
    __half* Wb = reinterpret_cast<__half*>(dyn + ST * A1_STAGE);         // [2][128][72]
    __half* Bb = Wb + 2 * WB_STRIDE;                                     // [ST][64][72]

    int tid = threadIdx.x;
    int warp = tid >> 5, lane = tid & 31;
    int wm = warp >> 1, wn = warp & 1;            // 4m x 2n warp grid
    int row0 = blockIdx.x * 128;
    int ksl = blockIdx.y;
    int kbase = ksl * (NN / KSPLIT1);             // 2048
    float acc[2][4][4] = {};
    const unsigned char* Ag = g_adj8 + (size_t)row0 * NN;

    auto load_tiles = [&](int s, int k0) {
        unsigned char* As = A8 + s * A1_STAGE;
        __half* Bs = Bb + s * B1_STRIDE;
#pragma unroll
        for (int i = 0; i < 2; ++i) {             // A: 128 rows x 64B
            int c = tid + i * 256;
            int r = c >> 2, col = (c & 3) * 16;
            cp16(As + r * 64 + col, Ag + (size_t)r * NN + k0 + col);
        }
#pragma unroll
        for (int i = 0; i < 2; ++i) {             // B: 64 rows x 128B
            int c = tid + i * 256;
            int r = c >> 3, col = (c & 7) * 8;
            cp16(Bs + r * 72 + col, g_z1 + (size_t)(k0 + r) * FHID + col);
        }
    };

#pragma unroll
    for (int s = 0; s < ST - 1; ++s) { load_tiles(s, kbase + s * KT); cp_commit(); }
    cp_wait_2();
    __syncthreads();
    dequant_stage(A8, Wb, warp, lane);            // stage 0 -> Wb[0]

    const int NIT = (NN / KSPLIT1) / KT;          // 32
    for (int it = 0; it < NIT; ++it) {
        if (it + 3 < NIT) load_tiles((it + 3) & (ST - 1), kbase + (it + 3) * KT);
        cp_commit();
        cp_wait_2();                              // stages <= it+1 arrived
        __syncthreads();                          // sync1

        if (it + 1 < NIT)                         // convert next stage (overlaps MMA issue)
            dequant_stage(A8 + ((it + 1) & (ST - 1)) * A1_STAGE,
                          Wb + ((it + 1) & 1) * WB_STRIDE, warp, lane);

        __half* As = Wb + (it & 1) * WB_STRIDE;
        __half* Bs = Bb + (it & (ST - 1)) * B1_STRIDE;
        int j = lane >> 3;                        // x4.trans lane group
#pragma unroll
        for (int ks = 0; ks < 4; ++ks) {
            uint32_t a[2][4], b[4][2];
#pragma unroll
            for (int mt = 0; mt < 2; ++mt) {
                unsigned ad = smem_u32(As + (wm * 32 + mt * 16 + (lane & 15)) * 72
                                          + ks * 16 + (lane >> 4) * 8);
                ldmatrix_x4(a[mt][0], a[mt][1], a[mt][2], a[mt][3], ad);
            }
#pragma unroll
            for (int nt2 = 0; nt2 < 2; ++nt2) {   // each x4.trans covers 2 nt tiles
                unsigned bd = smem_u32(Bs + (ks * 16 + (j & 1) * 8 + (lane & 7)) * 72
                                          + wn * 32 + nt2 * 16 + (j >> 1) * 8);
                ldmatrix_x4_trans(b[nt2 * 2][0], b[nt2 * 2][1],
                                  b[nt2 * 2 + 1][0], b[nt2 * 2 + 1][1], bd);
            }
#pragma unroll
            for (int mt = 0; mt < 2; ++mt)
#pragma unroll
                for (int nt = 0; nt < 4; ++nt)
                    mma_f16(acc[mt][nt], a[mt][0], a[mt][1], a[mt][2], a[mt][3],
                            b[nt][0], b[nt][1]);
        }
        __syncthreads();                          // sync2
    }

    // write fp32 partials (fold 1/255)
#pragma unroll
    for (int mt = 0; mt < 2; ++mt) {
#pragma unroll
        for (int nt = 0; nt < 4; ++nt) {
            int cbase = wn * 32 + nt * 8 + (lane & 3) * 2;
#pragma unroll
            for (int half = 0; half < 2; ++half) {
                int r = wm * 32 + mt * 16 + (lane >> 2) + half * 8;
                float2 v = make_float2(acc[mt][nt][half * 2 + 0] * INV255,
                                       acc[mt][nt][half * 2 + 1] * INV255);
                *reinterpret_cast<float2*>(&g_part1[ksl][row0 + r][cbase]) = v;
            }
        }
    }

    // last-CTA fused epilogue (z2f in fp32)
    __threadfence();
    __syncthreads();
    __shared__ int is_last;
    if (tid == 0) is_last = (atomicAdd(&g_cnt1[blockIdx.x], 1) == KSPLIT1 - 1);
    __syncthreads();
    if (!is_last) return;
    __threadfence();
    int seg = tid & 7;                            // 8 threads per row
#pragma unroll
    for (int rr = 0; rr < 4; ++rr) {
        int row = row0 + rr * 32 + (tid >> 3);
        float dd = g_d[row];
        float u[8] = {};
#pragma unroll
        for (int s = 0; s < KSPLIT1; ++s) {
            float4 a = *reinterpret_cast<const float4*>(&g_part1[s][row][seg * 8]);
            float4 b = *reinterpret_cast<const float4*>(&g_part1[s][row][seg * 8 + 4]);
            u[0] += a.x; u[1] += a.y; u[2] += a.z; u[3] += a.w;
            u[4] += b.x; u[5] += b.y; u[6] += b.z; u[7] += b.w;
        }
        float s0 = 0.f, s1 = 0.f;
#pragma unroll
        for (int jj = 0; jj < 8; ++jj) {
            int c = seg * 8 + jj;
            float h = fmaxf(dd * u[jj] + b1[c], 0.f);
            s0 += h * W2[c * 2 + 0];
            s1 += h * W2[c * 2 + 1];
        }
        for (int o = 4; o; o >>= 1) {
            s0 += __shfl_xor_sync(0xFFFFFFFFu, s0, o);
            s1 += __shfl_xor_sync(0xFFFFFFFFu, s1, o);
        }
        if (seg == 0)
            *reinterpret_cast<float2*>(&g_z2f[row * 2]) = make_float2(dd * s0, dd * s1);
    }
    if (tid == 0) g_cnt1[blockIdx.x] = 0;         // reset for next graph replay
}

// ---------------------------------------------------------------------------
// Kernel 4: agg2 direct fp32:  out = d ⊙ ((1/255)·adj8 @ z2f) + b2
// 512 threads, 32 rows/CTA (16 warps x 2 rows) -> grid 256, single wave.
// t=0 adj prefetched before staging barrier; loads software-pipelined.
// ---------------------------------------------------------------------------
__global__ __launch_bounds__(512) void k_agg2_fma(const float* __restrict__ b2,
                                                  float* __restrict__ out) {
    extern __shared__ __align__(16) unsigned char dyn[];
    float2* z2s = reinterpret_cast<float2*>(dyn);   // padded index k -> k + (k>>4)
    int tid = threadIdx.x, warp = tid >> 5, lane = tid & 31;

    int row0 = blockIdx.x * 32 + warp * 2;
    const unsigned char* Ar = g_adj8 + (size_t)row0 * NN;

    // prefetch t=0 adjacency chunks (overlaps the staging below)
    uint4 aw[2];
#pragma unroll
    for (int q = 0; q < 2; ++q)
        aw[q] = *reinterpret_cast<const uint4*>(Ar + (size_t)q * NN + lane * 16);

    // stage z2f (8192 float2) into padded smem
    {
        const uint4* src = reinterpret_cast<const uint4*>(g_z2f);
        for (int i = tid; i < NN / 2; i += 512) {
            uint4 v = src[i];
            int k = i * 2;
            int kp = k + (k >> 4);
            *reinterpret_cast<uint2*>(&z2s[kp])     = make_uint2(v.x, v.y);
            *reinterpret_cast<uint2*>(&z2s[kp + 1]) = make_uint2(v.z, v.w);
        }
    }
    __syncthreads();

    float acc[2][2] = {};

#pragma unroll 2
    for (int t = 0; t < 16; ++t) {
        uint4 awn[2];
        if (t < 15) {
#pragma unroll
            for (int q = 0; q < 2; ++q)
                awn[q] = *reinterpret_cast<const uint4*>(
                    Ar + (size_t)q * NN + (t + 1) * 512 + lane * 16);
        }
        int kbase = t * 512 + lane * 16;
        int kp = kbase + (kbase >> 4);
#pragma unroll
        for (int e = 0; e < 16; ++e) {
            float2 z = z2s[kp + e];
            const int wi = e >> 2, bi = e & 3;
#pragma unroll
            for (int q = 0; q < 2; ++q) {
                uint32_t wv = (wi == 0) ? aw[q].x : (wi == 1) ? aw[q].y
                            : (wi == 2) ? aw[q].z : aw[q].w;
                float f = __uint_as_float(__byte_perm(wv, 0x4B000000u, 0x7540u | bi))
                          - 8388608.f;
                acc[q][0] = fmaf(f, z.x, acc[q][0]);
                acc[q][1] = fmaf(f, z.y, acc[q][1]);
            }
        }
        aw[0] = awn[0];
        aw[1] = awn[1];
    }

    // warp reduce (each lane holds a disjoint K-subset partial)
#pragma unroll
    for (int q = 0; q < 2; ++q)
#pragma unroll
        for (int c = 0; c < 2; ++c)
            for (int o = 16; o; o >>= 1)
                acc[q][c] += __shfl_xor_sync(0xFFFFFFFFu, acc[q][c], o);

    if (lane == 0) {
        float bb0 = b2[0], bb1 = b2[1];
#pragma unroll
        for (int q = 0; q < 2; ++q) {
            int r = row0 + q;
            float dd = g_d[r] * INV255;
            *reinterpret_cast<float2*>(&out[r * 2]) =
                make_float2(dd * acc[q][0] + bb0, dd * acc[q][1] + bb1);
        }
    }
}

// ---------------------------------------------------------------------------
// Launch
// ---------------------------------------------------------------------------
extern "C" void kernel_launch(void* const* d_in, const int* in_sizes, int n_in,
                              void* d_out, int out_size) {
    const float *x = nullptr, *adj = nullptr, *W1 = nullptr, *b1 = nullptr,
                *W2 = nullptr, *b2 = nullptr;
    for (int i = 0; i < n_in; ++i) {
        switch (in_sizes[i]) {
            case NN * FIN:    x   = (const float*)d_in[i]; break;
            case 67108864:    adj = (const float*)d_in[i]; break;
            case FIN * FHID:  W1  = (const float*)d_in[i]; break;
            case FHID:        b1  = (const float*)d_in[i]; break;
            case FHID * FOUT: W2  = (const float*)d_in[i]; break;
            case FOUT:        b2  = (const float*)d_in[i]; break;
            default: break;
        }
    }
    float* out = (float*)d_out;

    const int smem1 = ST * A1_STAGE + 2 * WB_STRIDE * 2 + ST * B1_STRIDE * 2;  // 106496
    const int smem2 = (NN + NN / 16) * 8;                                       // 69632
    cudaFuncSetAttribute(k_agg1, cudaFuncAttributeMaxDynamicSharedMemorySize, smem1);
    cudaFuncSetAttribute(k_agg2_fma, cudaFuncAttributeMaxDynamicSharedMemorySize, smem2);

    k_rowsum_convert<<<NN, 512>>>(adj);
    k_xw1<<<NN / 16, 256>>>(x, W1);
    k_agg1<<<dim3(NN / 128, KSPLIT1), 256, smem1>>>(b1, W2);
    k_agg2_fma<<<NN / 32, 512, smem2>>>(b2, out);
}